// round 2
// baseline (speedup 1.0000x reference)
#include <cuda_runtime.h>
#include <cuda_fp16.h>
#include <stdint.h>

// W4A16 grouped-dequant GEMM:  out[32, 28672] = x[32, 8192] @ dequant(qweight) + bias
// Harness promotes fp16 tensors to float32: x, scales, bias, out are all float*.
// qweight: (K/8, N) int32, 8 int4 nibbles along K per word, zero-point 8,
// scales: (K/128, N) per-group.
//
// Strategy: mma.sync.m16n8k16 (f16 x f16 -> f32). K is permuted (per 32-k block)
// so each int32 word maps exactly onto one lane's B-fragment registers for two
// k16 steps -> weights go GMEM -> registers -> tensor core with no smem staging.
// x is staged in smem (converted f32->f16) with the same permutation, read via
// ldmatrix.

namespace {

constexpr int M      = 32;
constexpr int K      = 8192;
constexpr int N      = 28672;
constexpr int KTILE  = 128;   // = group size, so one scale load per iter
constexpr int NTILE  = 128;   // per block
constexpr int NWARP  = 32;    // columns per warp
constexpr int THREADS = 128;  // 4 warps
constexpr int NITER  = K / KTILE;  // 64
constexpr int SAS    = (KTILE + 8) * 2;  // 272 bytes per sA row (pad: conflict-free ldmatrix)

__device__ __forceinline__ void ldmatrix_x4(uint32_t (&a)[4], const void* p) {
    uint32_t addr = (uint32_t)__cvta_generic_to_shared(p);
    asm volatile("ldmatrix.sync.aligned.m8n8.x4.shared.b16 {%0,%1,%2,%3}, [%4];"
                 : "=r"(a[0]), "=r"(a[1]), "=r"(a[2]), "=r"(a[3])
                 : "r"(addr));
}

__device__ __forceinline__ void mma16816(float (&d)[4], const uint32_t (&a)[4],
                                         uint32_t b0, uint32_t b1) {
    asm volatile(
        "mma.sync.aligned.m16n8k16.row.col.f32.f16.f16.f32 "
        "{%0,%1,%2,%3}, {%4,%5,%6,%7}, {%8,%9}, {%0,%1,%2,%3};"
        : "+f"(d[0]), "+f"(d[1]), "+f"(d[2]), "+f"(d[3])
        : "r"(a[0]), "r"(a[1]), "r"(a[2]), "r"(a[3]), "r"(b0), "r"(b1));
}

__device__ __forceinline__ uint32_t deq_pair(uint32_t w, int sh, __half2 h1032, __half2 s2) {
    // picks nibbles (sh/4) and (sh/4 + 4) of w -> fp16x2 of (q-8)*s, exact.
    uint32_t q = ((w >> sh) & 0x000F000Fu) | 0x64006400u;   // (1024+q_lo, 1024+q_hi)
    __half2 h = *reinterpret_cast<__half2*>(&q);
    __half2 v = __hmul2(__hsub2(h, h1032), s2);
    return *reinterpret_cast<uint32_t*>(&v);
}

__device__ __forceinline__ uint32_t pack_h2(float a, float b) {
    __half2 h = __floats2half2_rn(a, b);
    return *reinterpret_cast<uint32_t*>(&h);
}

__global__ void __launch_bounds__(THREADS)
qlinear_w4a16(const float* __restrict__ x,
              const uint32_t* __restrict__ qw,
              const float* __restrict__ scales,
              const float* __restrict__ bias,
              float* __restrict__ out)
{
    __shared__ __align__(16) uint8_t sA[M * SAS];

    const int tid  = threadIdx.x;
    const int warp = tid >> 5;
    const int lane = tid & 31;
    const int nb   = blockIdx.x * NTILE + warp * NWARP;
    const int c    = lane >> 2;   // 0..7  (n within n8 tile)
    const int t    = lane & 3;    // 0..3  (k quad / word role)

    // x-tile loader mapping: thread handles row xm, word-spans [xwb, xwb+4)
    const int xm  = tid >> 2;          // 0..31
    const int xwb = (tid & 3) * 4;     // 0,4,8,12

    const __half2 h1032 = __half2half2(__ushort_as_half((unsigned short)0x6408)); // 1032.0

    // per-lane ldmatrix address components
    const int lm_row = (lane & 15);
    const int lm_hi  = (lane & 16) ? 16 : 0;

    float acc[2][4][4];
    #pragma unroll
    for (int i = 0; i < 2; i++)
        #pragma unroll
        for (int j = 0; j < 4; j++)
            #pragma unroll
            for (int l = 0; l < 4; l++) acc[i][j][l] = 0.0f;

    for (int it = 0; it < NITER; ++it) {
        const int k0    = it * KTILE;
        const int krow0 = it * (KTILE / 8);   // qweight row base (16 rows per iter)

        // ---- issue all global loads for this iter up front (MLP) ----
        // weights: lane (c,t) loads word (krow0 + kk*4 + t, nb + nt*8 + c)
        uint32_t w[4][4];
        #pragma unroll
        for (int kk = 0; kk < 4; kk++)
            #pragma unroll
            for (int nt = 0; nt < 4; nt++)
                w[kk][nt] = qw[(size_t)(krow0 + kk * 4 + t) * N + (nb + nt * 8 + c)];

        // scales (one group per iter), f32 -> f16 (lossless: orig was f16)
        __half2 s2[4];
        #pragma unroll
        for (int nt = 0; nt < 4; nt++)
            s2[nt] = __half2half2(__float2half_rn(scales[(size_t)it * N + (nb + nt * 8 + c)]));

        // x tile: 8 f32 per word-span, 4 spans per thread = 32 floats
        float4 xr[4][2];
        #pragma unroll
        for (int j = 0; j < 4; j++) {
            const float* xp = x + (size_t)xm * K + k0 + (xwb + j) * 8;
            xr[j][0] = *reinterpret_cast<const float4*>(xp);
            xr[j][1] = *reinterpret_cast<const float4*>(xp + 4);
        }

        __syncthreads();   // previous tile fully consumed

        // ---- store x tile with k-permutation (f32 -> f16 pairs) ----
        // word-span wsp covers orig k [8*wsp, 8*wsp+8); within its 32-k chunk
        // (kk = wsp/4, tt = wsp&3) pairs go to byte slots:
        //   (x0,x4)->tt*4  (x1,x5)->16+tt*4  (x2,x6)->32+tt*4  (x3,x7)->48+tt*4
        #pragma unroll
        for (int j = 0; j < 4; j++) {
            const int wsp = xwb + j;
            uint32_t p0 = pack_h2(xr[j][0].x, xr[j][1].x);  // (x0,x4)
            uint32_t p1 = pack_h2(xr[j][0].y, xr[j][1].y);  // (x1,x5)
            uint32_t p2 = pack_h2(xr[j][0].z, xr[j][1].z);  // (x2,x6)
            uint32_t p3 = pack_h2(xr[j][0].w, xr[j][1].w);  // (x3,x7)
            uint8_t* base = sA + xm * SAS + (wsp >> 2) * 64 + (wsp & 3) * 4;
            *reinterpret_cast<uint32_t*>(base +  0) = p0;
            *reinterpret_cast<uint32_t*>(base + 16) = p1;
            *reinterpret_cast<uint32_t*>(base + 32) = p2;
            *reinterpret_cast<uint32_t*>(base + 48) = p3;
        }
        __syncthreads();   // tile ready

        // ---- compute: 4 x (k32 chunk) ----
        #pragma unroll
        for (int kk = 0; kk < 4; kk++) {
            // A fragments for the two k16 steps of this k32 chunk
            uint32_t a[2][2][4];   // [mtile][h][4]
            #pragma unroll
            for (int mt = 0; mt < 2; mt++)
                #pragma unroll
                for (int h = 0; h < 2; h++) {
                    const uint8_t* p = sA + (mt * 16 + lm_row) * SAS
                                     + kk * 64 + h * 32 + lm_hi;
                    ldmatrix_x4(a[mt][h], p);
                }

            #pragma unroll
            for (int nt = 0; nt < 4; nt++) {
                const uint32_t ww = w[kk][nt];
                // h=0 fragment: nibble pairs (0,4) -> b0, (1,5) -> b1
                uint32_t b00 = deq_pair(ww,  0, h1032, s2[nt]);
                uint32_t b01 = deq_pair(ww,  4, h1032, s2[nt]);
                // h=1 fragment: (2,6) -> b0, (3,7) -> b1
                uint32_t b10 = deq_pair(ww,  8, h1032, s2[nt]);
                uint32_t b11 = deq_pair(ww, 12, h1032, s2[nt]);

                mma16816(acc[0][nt], a[0][0], b00, b01);
                mma16816(acc[1][nt], a[1][0], b00, b01);
                mma16816(acc[0][nt], a[0][1], b10, b11);
                mma16816(acc[1][nt], a[1][1], b10, b11);
            }
        }
    }

    // ---- epilogue: add bias, store f32 ----
    #pragma unroll
    for (int mt = 0; mt < 2; mt++)
        #pragma unroll
        for (int nt = 0; nt < 4; nt++) {
            const int n  = nb + nt * 8 + t * 2;
            const int m0 = mt * 16 + c;
            float b0 = bias[n], b1 = bias[n + 1];
            float2 r0 = make_float2(acc[mt][nt][0] + b0, acc[mt][nt][1] + b1);
            float2 r1 = make_float2(acc[mt][nt][2] + b0, acc[mt][nt][3] + b1);
            *reinterpret_cast<float2*>(out + (size_t)m0 * N + n)       = r0;
            *reinterpret_cast<float2*>(out + (size_t)(m0 + 8) * N + n) = r1;
        }
}

} // namespace

extern "C" void kernel_launch(void* const* d_in, const int* in_sizes, int n_in,
                              void* d_out, int out_size)
{
    const float*    x  = (const float*)d_in[0];
    const uint32_t* qw = (const uint32_t*)d_in[1];
    const float*    sc = (const float*)d_in[2];
    const float*    bs = (const float*)d_in[3];
    float*          o  = (float*)d_out;

    dim3 grid(N / NTILE);   // 224
    dim3 block(THREADS);    // 128
    qlinear_w4a16<<<grid, block>>>(x, qw, sc, bs, o);
}

// round 3
// speedup vs baseline: 2.3816x; 2.3816x over previous
#include <cuda_runtime.h>
#include <cuda_fp16.h>
#include <stdint.h>

// W4A16 grouped-dequant GEMM:  out[32, 28672] = x[32, 8192] @ dequant(qweight) + bias
// All fp16 tensors are promoted to float32 by the harness (x, scales, bias, out).
//
// 3-kernel plan (all cheap except main):
//   1. prep_a:  x (f32) -> fp16, k-permuted, materialized as per-lane mma A-fragment
//               register images in g_apack (512 KB, L2-resident).
//   2. qlinear_main: split-K=2 GEMM. Weights: GMEM->reg->dequant->mma (no smem).
//               A: 4x LDG.128 per k32-chunk from g_apack (L2). No __syncthreads.
//               Weight LDGs double-buffered one k128-tile ahead. Partials to g_part.
//   3. reduce_out: out = part0 + part1 + bias.

namespace {

constexpr int M       = 32;
constexpr int K       = 8192;
constexpr int N       = 28672;
constexpr int KTILE   = 128;             // = group size: one scale per iter
constexpr int NTILE   = 128;             // per block
constexpr int NWARP   = 32;              // columns per warp
constexpr int THREADS = 128;
constexpr int NITER   = K / KTILE;       // 64
constexpr int KSPLIT  = 2;
constexpr int NITER_S = NITER / KSPLIT;  // 32
constexpr int SAS     = (KTILE + 8) * 2; // prep smem row stride (bytes)

// A fragments: [iter][kk][mt][h][lane] as uint4 (4 mma regs)
__device__ uint4  g_apack[NITER * 4 * 2 * 2 * 32];       // 512 KB
__device__ float4 g_part4[KSPLIT * M * N / 4];           // 7.34 MB split-K partials

__device__ __forceinline__ void ldmatrix_x4(uint32_t (&a)[4], const void* p) {
    uint32_t addr = (uint32_t)__cvta_generic_to_shared(p);
    asm volatile("ldmatrix.sync.aligned.m8n8.x4.shared.b16 {%0,%1,%2,%3}, [%4];"
                 : "=r"(a[0]), "=r"(a[1]), "=r"(a[2]), "=r"(a[3])
                 : "r"(addr));
}

__device__ __forceinline__ void mma16816(float (&d)[4], const uint4& av,
                                         uint32_t b0, uint32_t b1) {
    asm volatile(
        "mma.sync.aligned.m16n8k16.row.col.f32.f16.f16.f32 "
        "{%0,%1,%2,%3}, {%4,%5,%6,%7}, {%8,%9}, {%0,%1,%2,%3};"
        : "+f"(d[0]), "+f"(d[1]), "+f"(d[2]), "+f"(d[3])
        : "r"(av.x), "r"(av.y), "r"(av.z), "r"(av.w), "r"(b0), "r"(b1));
}

__device__ __forceinline__ uint32_t deq_pair(uint32_t w, int sh, __half2 h1032, __half2 s2) {
    // nibbles (sh/4) and (sh/4 + 4) -> fp16x2 of (q-8)*s, exact
    uint32_t q = ((w >> sh) & 0x000F000Fu) | 0x64006400u;
    __half2 h = *reinterpret_cast<__half2*>(&q);
    __half2 v = __hmul2(__hsub2(h, h1032), s2);
    return *reinterpret_cast<uint32_t*>(&v);
}

__device__ __forceinline__ uint32_t pack_h2(float a, float b) {
    __half2 h = __floats2half2_rn(a, b);
    return *reinterpret_cast<uint32_t*>(&h);
}

// ---------------- prep: x -> packed A fragments ----------------
__global__ void __launch_bounds__(THREADS)
prep_a(const float* __restrict__ x)
{
    __shared__ __align__(16) uint8_t sA[M * SAS];

    const int tid  = threadIdx.x;
    const int warp = tid >> 5;
    const int lane = tid & 31;
    const int it   = blockIdx.x;       // 0..63
    const int k0   = it * KTILE;

    const int xm  = tid >> 2;          // row 0..31
    const int xwb = (tid & 3) * 4;     // word-span base

    float4 xr[4][2];
    #pragma unroll
    for (int j = 0; j < 4; j++) {
        const float* xp = x + (size_t)xm * K + k0 + (xwb + j) * 8;
        xr[j][0] = *reinterpret_cast<const float4*>(xp);
        xr[j][1] = *reinterpret_cast<const float4*>(xp + 4);
    }
    #pragma unroll
    for (int j = 0; j < 4; j++) {
        const int wsp = xwb + j;
        uint32_t p0 = pack_h2(xr[j][0].x, xr[j][1].x);
        uint32_t p1 = pack_h2(xr[j][0].y, xr[j][1].y);
        uint32_t p2 = pack_h2(xr[j][0].z, xr[j][1].z);
        uint32_t p3 = pack_h2(xr[j][0].w, xr[j][1].w);
        uint8_t* base = sA + xm * SAS + (wsp >> 2) * 64 + (wsp & 3) * 4;
        *reinterpret_cast<uint32_t*>(base +  0) = p0;
        *reinterpret_cast<uint32_t*>(base + 16) = p1;
        *reinterpret_cast<uint32_t*>(base + 32) = p2;
        *reinterpret_cast<uint32_t*>(base + 48) = p3;
    }
    __syncthreads();

    const int lm_row = (lane & 15);
    const int lm_hi  = (lane & 16) ? 16 : 0;
    const int kk     = warp;           // one k32 chunk per warp

    #pragma unroll
    for (int mt = 0; mt < 2; mt++)
        #pragma unroll
        for (int h = 0; h < 2; h++) {
            uint32_t a[4];
            ldmatrix_x4(a, sA + (mt * 16 + lm_row) * SAS + kk * 64 + h * 32 + lm_hi);
            const int f = ((it * 4 + kk) * 2 + mt) * 2 + h;
            g_apack[f * 32 + lane] = make_uint4(a[0], a[1], a[2], a[3]);
        }
}

// ---------------- main GEMM (split-K) ----------------
#define LOADW(buf, itv)                                                        \
    do {                                                                       \
        const int krow0_ = (itv) * (KTILE / 8);                                \
        _Pragma("unroll")                                                      \
        for (int kk_ = 0; kk_ < 4; kk_++)                                      \
            _Pragma("unroll")                                                  \
            for (int nt_ = 0; nt_ < 4; nt_++)                                  \
                (buf)[kk_ * 4 + nt_] =                                         \
                    qw[(size_t)(krow0_ + kk_ * 4 + t) * N + (nb + nt_ * 8 + c)]; \
    } while (0)

__global__ void __launch_bounds__(THREADS)
qlinear_main(const uint32_t* __restrict__ qw,
             const float* __restrict__ scales)
{
    const int tid  = threadIdx.x;
    const int warp = tid >> 5;
    const int lane = tid & 31;
    const int nb   = blockIdx.x * NTILE + warp * NWARP;
    const int split = blockIdx.y;
    const int it0  = split * NITER_S;
    const int c    = lane >> 2;
    const int t    = lane & 3;
    const int itEnd = it0 + NITER_S;

    const __half2 h1032 = __half2half2(__ushort_as_half((unsigned short)0x6408)); // 1032

    float acc[2][4][4];
    #pragma unroll
    for (int i = 0; i < 2; i++)
        #pragma unroll
        for (int j = 0; j < 4; j++)
            #pragma unroll
            for (int l = 0; l < 4; l++) acc[i][j][l] = 0.0f;

    uint32_t wb0[16], wb1[16];
    LOADW(wb0, it0);

    #define BODY(WCUR, WNXT, ITV)                                              \
    do {                                                                       \
        const int it_ = (ITV);                                                 \
        if (it_ + 1 < itEnd) { LOADW(WNXT, it_ + 1); }                         \
        __half2 s2[4];                                                         \
        _Pragma("unroll")                                                      \
        for (int nt = 0; nt < 4; nt++)                                         \
            s2[nt] = __half2half2(__float2half_rn(                             \
                scales[(size_t)it_ * N + (nb + nt * 8 + c)]));                 \
        _Pragma("unroll")                                                      \
        for (int kk = 0; kk < 4; kk++) {                                       \
            const uint4* ap = g_apack + (size_t)((it_ * 4 + kk) * 4) * 32 + lane; \
            uint4 a00 = ap[0];    /* mt0 h0 */                                 \
            uint4 a01 = ap[32];   /* mt0 h1 */                                 \
            uint4 a10 = ap[64];   /* mt1 h0 */                                 \
            uint4 a11 = ap[96];   /* mt1 h1 */                                 \
            _Pragma("unroll")                                                  \
            for (int nt = 0; nt < 4; nt++) {                                   \
                const uint32_t ww = (WCUR)[kk * 4 + nt];                       \
                uint32_t b00 = deq_pair(ww,  0, h1032, s2[nt]);                \
                uint32_t b01 = deq_pair(ww,  4, h1032, s2[nt]);                \
                uint32_t b10 = deq_pair(ww,  8, h1032, s2[nt]);                \
                uint32_t b11 = deq_pair(ww, 12, h1032, s2[nt]);                \
                mma16816(acc[0][nt], a00, b00, b01);                           \
                mma16816(acc[1][nt], a10, b00, b01);                           \
                mma16816(acc[0][nt], a01, b10, b11);                           \
                mma16816(acc[1][nt], a11, b10, b11);                           \
            }                                                                  \
        }                                                                      \
    } while (0)

    for (int i = 0; i < NITER_S; i += 2) {
        BODY(wb0, wb1, it0 + i);
        BODY(wb1, wb0, it0 + i + 1);
    }
    #undef BODY

    // partials (fp32) to scratch; reduce kernel adds splits + bias
    float* pp = reinterpret_cast<float*>(g_part4) + (size_t)split * M * N;
    #pragma unroll
    for (int mt = 0; mt < 2; mt++)
        #pragma unroll
        for (int nt = 0; nt < 4; nt++) {
            const int n  = nb + nt * 8 + t * 2;
            const int m0 = mt * 16 + c;
            *reinterpret_cast<float2*>(pp + (size_t)m0 * N + n) =
                make_float2(acc[mt][nt][0], acc[mt][nt][1]);
            *reinterpret_cast<float2*>(pp + (size_t)(m0 + 8) * N + n) =
                make_float2(acc[mt][nt][2], acc[mt][nt][3]);
        }
}

// ---------------- reduce: out = part0 + part1 + bias ----------------
__global__ void __launch_bounds__(256)
reduce_out(const float* __restrict__ bias, float* __restrict__ out)
{
    constexpr int TOT4 = M * N / 4;   // 229376
    const int i = blockIdx.x * 256 + threadIdx.x;
    if (i >= TOT4) return;
    float4 a = g_part4[i];
    float4 b = g_part4[TOT4 + i];
    float4 bv = reinterpret_cast<const float4*>(bias)[i % (N / 4)];
    reinterpret_cast<float4*>(out)[i] =
        make_float4(a.x + b.x + bv.x, a.y + b.y + bv.y,
                    a.z + b.z + bv.z, a.w + b.w + bv.w);
}

} // namespace

extern "C" void kernel_launch(void* const* d_in, const int* in_sizes, int n_in,
                              void* d_out, int out_size)
{
    const float*    x  = (const float*)d_in[0];
    const uint32_t* qw = (const uint32_t*)d_in[1];
    const float*    sc = (const float*)d_in[2];
    const float*    bs = (const float*)d_in[3];
    float*          o  = (float*)d_out;

    prep_a<<<NITER, THREADS>>>(x);                          // 64 blocks
    qlinear_main<<<dim3(N / NTILE, KSPLIT), THREADS>>>(qw, sc);  // 224 x 2
    reduce_out<<<(M * N / 4 + 255) / 256, 256>>>(bs, o);    // 896 blocks
}

// round 5
// speedup vs baseline: 2.5255x; 1.0604x over previous
#include <cuda_runtime.h>
#include <cuda_fp16.h>
#include <stdint.h>

// W4A16 grouped-dequant GEMM:  out[32, 28672] = x[32, 8192] @ dequant(qweight) + bias
// All fp16 tensors are promoted to float32 by the harness (x, scales, bias, out).
//
//   1. prep_a:       x (f32) -> fp16, k-permuted, materialized as per-lane mma
//                    A-fragment register images in g_apack (512 KB, L2-resident).
//   2. qlinear_main: split-K=2 GEMM. Weights: vectorized uint4 LDG (4 consecutive
//                    N columns per lane; mma tile nt covers physical cols {4c+nt}),
//                    EXACT dequant (hsub2 then hmul2 — no fp16 cancellation),
//                    A fragments register-prefetched one k32 chunk ahead.
//                    No smem, no __syncthreads.
//   3. reduce_out:   out[phys] = part0[virt] + part1[virt] + bias[phys]
//                    (un-permutes the N-column interleave; perm stays within 128B lines).

namespace {

constexpr int M       = 32;
constexpr int K       = 8192;
constexpr int N       = 28672;
constexpr int KTILE   = 128;             // = group size: one scale per iter
constexpr int NTILE   = 128;             // per block
constexpr int NWARP   = 32;              // columns per warp
constexpr int THREADS = 128;
constexpr int NITER   = K / KTILE;       // 64
constexpr int KSPLIT  = 2;
constexpr int NITER_S = NITER / KSPLIT;  // 32
constexpr int SAS     = (KTILE + 8) * 2; // prep smem row stride (bytes)

// A fragments: [iter][kk][mt][h][lane] as uint4 (4 mma regs)
__device__ uint4  g_apack[NITER * 4 * 2 * 2 * 32];       // 512 KB
__device__ float4 g_part4[KSPLIT * M * N / 4];           // split-K partials

__device__ __forceinline__ void ldmatrix_x4(uint32_t (&a)[4], const void* p) {
    uint32_t addr = (uint32_t)__cvta_generic_to_shared(p);
    asm volatile("ldmatrix.sync.aligned.m8n8.x4.shared.b16 {%0,%1,%2,%3}, [%4];"
                 : "=r"(a[0]), "=r"(a[1]), "=r"(a[2]), "=r"(a[3])
                 : "r"(addr));
}

__device__ __forceinline__ void mma16816(float (&d)[4], const uint4& av,
                                         uint32_t b0, uint32_t b1) {
    asm volatile(
        "mma.sync.aligned.m16n8k16.row.col.f32.f16.f16.f32 "
        "{%0,%1,%2,%3}, {%4,%5,%6,%7}, {%8,%9}, {%0,%1,%2,%3};"
        : "+f"(d[0]), "+f"(d[1]), "+f"(d[2]), "+f"(d[3])
        : "r"(av.x), "r"(av.y), "r"(av.z), "r"(av.w), "r"(b0), "r"(b1));
}

// nibbles (sh/4) and (sh/4+4) -> fp16x2 of (q-8)*s, EXACT:
// (1024+q) - 1032 is exact in fp16 (integers), then one rounded multiply.
__device__ __forceinline__ uint32_t deq_pair(uint32_t w, int sh, __half2 h1032, __half2 s2) {
    uint32_t q = ((w >> sh) & 0x000F000Fu) | 0x64006400u;
    __half2 h = *reinterpret_cast<__half2*>(&q);
    __half2 v = __hmul2(__hsub2(h, h1032), s2);
    return *reinterpret_cast<uint32_t*>(&v);
}

__device__ __forceinline__ uint32_t pack_h2(float a, float b) {
    __half2 h = __floats2half2_rn(a, b);
    return *reinterpret_cast<uint32_t*>(&h);
}

// ---------------- prep: x -> packed A fragments ----------------
__global__ void __launch_bounds__(THREADS)
prep_a(const float* __restrict__ x)
{
    __shared__ __align__(16) uint8_t sA[M * SAS];

    const int tid  = threadIdx.x;
    const int warp = tid >> 5;
    const int lane = tid & 31;
    const int it   = blockIdx.x;       // 0..63
    const int k0   = it * KTILE;

    const int xm  = tid >> 2;          // row 0..31
    const int xwb = (tid & 3) * 4;     // word-span base

    float4 xr[4][2];
    #pragma unroll
    for (int j = 0; j < 4; j++) {
        const float* xp = x + (size_t)xm * K + k0 + (xwb + j) * 8;
        xr[j][0] = *reinterpret_cast<const float4*>(xp);
        xr[j][1] = *reinterpret_cast<const float4*>(xp + 4);
    }
    #pragma unroll
    for (int j = 0; j < 4; j++) {
        const int wsp = xwb + j;
        uint32_t p0 = pack_h2(xr[j][0].x, xr[j][1].x);
        uint32_t p1 = pack_h2(xr[j][0].y, xr[j][1].y);
        uint32_t p2 = pack_h2(xr[j][0].z, xr[j][1].z);
        uint32_t p3 = pack_h2(xr[j][0].w, xr[j][1].w);
        uint8_t* base = sA + xm * SAS + (wsp >> 2) * 64 + (wsp & 3) * 4;
        *reinterpret_cast<uint32_t*>(base +  0) = p0;
        *reinterpret_cast<uint32_t*>(base + 16) = p1;
        *reinterpret_cast<uint32_t*>(base + 32) = p2;
        *reinterpret_cast<uint32_t*>(base + 48) = p3;
    }
    __syncthreads();

    const int lm_row = (lane & 15);
    const int lm_hi  = (lane & 16) ? 16 : 0;
    const int kk     = warp;           // one k32 chunk per warp

    #pragma unroll
    for (int mt = 0; mt < 2; mt++)
        #pragma unroll
        for (int h = 0; h < 2; h++) {
            uint32_t a[4];
            ldmatrix_x4(a, sA + (mt * 16 + lm_row) * SAS + kk * 64 + h * 32 + lm_hi);
            const int f = ((it * 4 + kk) * 2 + mt) * 2 + h;
            g_apack[f * 32 + lane] = make_uint4(a[0], a[1], a[2], a[3]);
        }
}

// ---------------- main GEMM (split-K) ----------------
// wb: 4 x uint4; wb[kk] = qw[krow0+kk*4+t][nc0 .. nc0+3] (4 consecutive cols)
#define LOADW(buf, itv)                                                        \
    do {                                                                       \
        const int krow0_ = (itv) * (KTILE / 8);                                \
        _Pragma("unroll")                                                      \
        for (int kk_ = 0; kk_ < 4; kk_++)                                      \
            (buf)[kk_] = *reinterpret_cast<const uint4*>(                      \
                qw + (size_t)(krow0_ + kk_ * 4 + t) * N + nc0);                \
    } while (0)

#define LOADA(dst, itv, kkv)                                                   \
    do {                                                                       \
        const uint4* ap_ = g_apack + (size_t)(((itv) * 4 + (kkv)) * 4) * 32 + lane; \
        (dst)[0] = ap_[0];   /* mt0 h0 */                                      \
        (dst)[1] = ap_[32];  /* mt0 h1 */                                      \
        (dst)[2] = ap_[64];  /* mt1 h0 */                                      \
        (dst)[3] = ap_[96];  /* mt1 h1 */                                      \
    } while (0)

__global__ void __launch_bounds__(THREADS)
qlinear_main(const uint32_t* __restrict__ qw,
             const float* __restrict__ scales)
{
    const int tid  = threadIdx.x;
    const int warp = tid >> 5;
    const int lane = tid & 31;
    const int nb   = blockIdx.x * NTILE + warp * NWARP;  // physical col base
    const int split = blockIdx.y;
    const int it0  = split * NITER_S;
    const int c    = lane >> 2;
    const int t    = lane & 3;
    const int nc0  = nb + 4 * c;       // this lane's 4-column base (physical)
    const int itEnd = it0 + NITER_S;

    const __half2 h1032 = __half2half2(__ushort_as_half((unsigned short)0x6408)); // 1032

    float acc[2][4][4];
    #pragma unroll
    for (int i = 0; i < 2; i++)
        #pragma unroll
        for (int j = 0; j < 4; j++)
            #pragma unroll
            for (int l = 0; l < 4; l++) acc[i][j][l] = 0.0f;

    uint4 wb0[4], wb1[4];
    uint4 aC[4], aN[4];
    LOADW(wb0, it0);
    LOADA(aC, it0, 0);

    #define BODY(WCUR, WNXT, ITV)                                              \
    do {                                                                       \
        const int it_ = (ITV);                                                 \
        const int itn_ = (it_ + 1 < itEnd) ? it_ + 1 : it_;                    \
        if (it_ + 1 < itEnd) { LOADW(WNXT, it_ + 1); }                         \
        float4 sc4 = *reinterpret_cast<const float4*>(                         \
            scales + (size_t)it_ * N + nc0);                                   \
        __half2 s2[4];                                                         \
        _Pragma("unroll")                                                      \
        for (int nt = 0; nt < 4; nt++)                                         \
            s2[nt] = __half2half2(__float2half_rn((&sc4.x)[nt]));              \
        _Pragma("unroll")                                                      \
        for (int kk = 0; kk < 4; kk++) {                                       \
            /* prefetch next k32 chunk's A fragments */                        \
            const int pit = (kk == 3) ? itn_ : it_;                            \
            const int pkk = (kk + 1) & 3;                                      \
            LOADA(aN, pit, pkk);                                               \
            const uint4 ww4 = (WCUR)[kk];                                      \
            _Pragma("unroll")                                                  \
            for (int nt = 0; nt < 4; nt++) {                                   \
                const uint32_t ww = (&ww4.x)[nt];                              \
                uint32_t b00 = deq_pair(ww,  0, h1032, s2[nt]);                \
                uint32_t b01 = deq_pair(ww,  4, h1032, s2[nt]);                \
                uint32_t b10 = deq_pair(ww,  8, h1032, s2[nt]);                \
                uint32_t b11 = deq_pair(ww, 12, h1032, s2[nt]);                \
                mma16816(acc[0][nt], aC[0], b00, b01);                         \
                mma16816(acc[1][nt], aC[2], b00, b01);                         \
                mma16816(acc[0][nt], aC[1], b10, b11);                         \
                mma16816(acc[1][nt], aC[3], b10, b11);                         \
            }                                                                  \
            aC[0] = aN[0]; aC[1] = aN[1]; aC[2] = aN[2]; aC[3] = aN[3];        \
        }                                                                      \
    } while (0)

    for (int i = 0; i < NITER_S; i += 2) {
        BODY(wb0, wb1, it0 + i);
        BODY(wb1, wb0, it0 + i + 1);
    }
    #undef BODY

    // partials (fp32) to scratch in VIRTUAL column layout: virt = nt*8 + 2t + u.
    // physical col of virt v (within 32-col group) = 4*(v&7) ... see reduce.
    float* pp = reinterpret_cast<float*>(g_part4) + (size_t)split * M * N;
    #pragma unroll
    for (int mt = 0; mt < 2; mt++)
        #pragma unroll
        for (int nt = 0; nt < 4; nt++) {
            const int n  = nb + nt * 8 + t * 2;
            const int m0 = mt * 16 + c;
            *reinterpret_cast<float2*>(pp + (size_t)m0 * N + n) =
                make_float2(acc[mt][nt][0], acc[mt][nt][1]);
            *reinterpret_cast<float2*>(pp + (size_t)(m0 + 8) * N + n) =
                make_float2(acc[mt][nt][2], acc[mt][nt][3]);
        }
}

// ---------------- reduce: out[phys] = sum parts[virt] + bias[phys] ----------------
// physical q (0..31) = 4*cv + nt  <->  virtual v = nt*8 + cv
__global__ void __launch_bounds__(256)
reduce_out(const float* __restrict__ bias, float* __restrict__ out)
{
    const int idx = blockIdx.x * 256 + threadIdx.x;   // element index (m, p)
    if (idx >= M * N) return;
    const int m = idx / N;
    const int p = idx % N;
    const int grp = p & ~31;
    const int q   = p & 31;
    const int v = (q & 3) * 8 + (q >> 2);   // virt within 32-col group
    const float* part = reinterpret_cast<const float*>(g_part4);
    const size_t pi = (size_t)m * N + grp + v;
    float val = part[pi] + part[(size_t)M * N + pi] + bias[p];
    out[(size_t)m * N + p] = val;
}

} // namespace

extern "C" void kernel_launch(void* const* d_in, const int* in_sizes, int n_in,
                              void* d_out, int out_size)
{
    const float*    x  = (const float*)d_in[0];
    const uint32_t* qw = (const uint32_t*)d_in[1];
    const float*    sc = (const float*)d_in[2];
    const float*    bs = (const float*)d_in[3];
    float*          o  = (float*)d_out;

    prep_a<<<NITER, THREADS>>>(x);                               // 64 blocks
    qlinear_main<<<dim3(N / NTILE, KSPLIT), THREADS>>>(qw, sc);  // 224 x 2
    reduce_out<<<(M * N + 255) / 256, 256>>>(bs, o);             // 3584 blocks
}